// round 16
// baseline (speedup 1.0000x reference)
#include <cuda_runtime.h>
#include <cuda_fp16.h>
#include <cstdint>
#include <cstddef>

// Problem constants
#define M_DIM 8192
#define K_DIM 4096
#define N_DIM 11008
#define NPACK (N_DIM / 8)
#define KPACK (K_DIM / 8)

#define TK16 (K_DIM / 16)      // 256 k16-tiles

// GEMM tiling: block 128x128x32, 8 warps (2M x 4N), warp tile 64x32
#define BM 128
#define BN 128
#define BK 32
#define NT (K_DIM / BK)        // 128
#define MT_TILES (M_DIM / BM)  // 64
#define NT_TILES (N_DIM / BN)  // 86

// Device scratch (allocation-free rule)
// A in mma-fragment order: [tm16][tk16][lane]{a0,a1,a2,a3} (16B per lane)
__device__ __half g_af[(size_t)M_DIM * K_DIM];
// W in PAIRED fragment order: [tnp16][tk16][lane]{b0_even,b1_even,b0_odd,b1_odd}
__device__ __half g_wf[(size_t)K_DIM * N_DIM];

// ---------------------------------------------------------------------------
// Fused prep kernel: blocks [0,512) convert x -> A-fragment fp16;
// blocks [512, 512+22016) dequant W -> paired-fragment fp16.
// Both parts are memory-bound; fusing them into one launch overlaps them.
// ---------------------------------------------------------------------------
__global__ void prep_kernel(const float* __restrict__ x,
                            const int* __restrict__ qweight,
                            const int* __restrict__ qzeros,
                            const void* __restrict__ scales_raw) {
    if (blockIdx.x < 512) {
        // ---- convert_x part (verified R13) ----
        const int tm   = blockIdx.x;              // 0..511
        const int lane = threadIdx.x & 31;
        const int tkb  = threadIdx.x >> 5;        // 0..7
        const int r = lane >> 2, c = lane & 3;
        const int m0 = tm * 16;

        const float* row0 = x + (size_t)(m0 + r) * K_DIM + 2 * c;
        const float* row8 = row0 + (size_t)8 * K_DIM;
        uint4* dst = (uint4*)g_af + ((size_t)tm * TK16) * 32 + lane;

#pragma unroll 4
        for (int tk16 = tkb; tk16 < TK16; tk16 += 8) {
            const int k0 = tk16 * 16;
            float2 f0 = *(const float2*)(row0 + k0);
            float2 f1 = *(const float2*)(row8 + k0);
            float2 f2 = *(const float2*)(row0 + k0 + 8);
            float2 f3 = *(const float2*)(row8 + k0 + 8);
            __half2 h0 = __floats2half2_rn(f0.x, f0.y);
            __half2 h1 = __floats2half2_rn(f1.x, f1.y);
            __half2 h2 = __floats2half2_rn(f2.x, f2.y);
            __half2 h3 = __floats2half2_rn(f3.x, f3.y);
            uint4 u;
            u.x = *(uint32_t*)&h0; u.y = *(uint32_t*)&h1;
            u.z = *(uint32_t*)&h2; u.w = *(uint32_t*)&h3;
            dst[(size_t)tk16 * 32] = u;
        }
    } else {
        // ---- dequant part (verified R15) ----
        int idx = blockIdx.x - 512;               // 0..22015
        int nblk = idx % 43;
        int pr   = idx / 43;                      // 0..511
        int n  = nblk * 256 + threadIdx.x;
        int g  = pr >> 4;

        const float* sf = (const float*)scales_raw;
        float probe = sf[0];
        bool is_f32 = (probe > 5e-4f && probe < 5e-2f);

        uint32_t q  = (uint32_t)qweight[(size_t)pr * N_DIM + n];
        uint32_t zq = (uint32_t)qzeros[(size_t)g * NPACK + (n >> 3)];
        float z = (float)((zq >> (4 * (n & 7))) & 15u);
        float s = is_f32 ? sf[(size_t)g * N_DIM + n]
                         : __half2float(((const __half*)scales_raw)[(size_t)g * N_DIM + n]);

        int tnp    = n >> 4;
        int odd    = (n >> 3) & 1;
        int tk16   = pr >> 1;
        int regsel = pr & 1;
        size_t base = (((size_t)tnp * TK16 + tk16) * 32 + 4 * (n & 7)) * 8
                      + odd * 4 + regsel * 2;

#pragma unroll
        for (int p = 0; p < 4; p++) {
            float w0 = ((float)((q >> (8 * p))     & 15u) - z) * s;
            float w1 = ((float)((q >> (8 * p + 4)) & 15u) - z) * s;
            *(__half2*)(g_wf + base + (size_t)p * 8) = __floats2half2_rn(w0, w1);
        }
    }
}

// ---------------------------------------------------------------------------
// mma helper
// ---------------------------------------------------------------------------
__device__ __forceinline__ void mma16816(float* c, uint32_t a0, uint32_t a1,
                                         uint32_t a2, uint32_t a3,
                                         uint32_t b0, uint32_t b1) {
    asm volatile(
        "mma.sync.aligned.m16n8k16.row.col.f32.f16.f16.f32 "
        "{%0,%1,%2,%3}, {%4,%5,%6,%7}, {%8,%9}, {%0,%1,%2,%3};"
        : "+f"(c[0]), "+f"(c[1]), "+f"(c[2]), "+f"(c[3])
        : "r"(a0), "r"(a1), "r"(a2), "r"(a3), "r"(b0), "r"(b1));
}

// ---------------------------------------------------------------------------
// Kernel 2: fragment GEMM, software-pipelined (B loads lead), unroll 2.
// ---------------------------------------------------------------------------
__global__ __launch_bounds__(256, 2)
void gemm_kernel(float* __restrict__ out) {
    const int tid  = threadIdx.x;
    const int lane = tid & 31;
    const int wid  = tid >> 5;
    const int warp_m = wid & 1;    // 0..1 (64 rows = 4 m16 tiles each)
    const int warp_n = wid >> 1;   // 0..3 (32 cols = 2 n8-pairs each)

    // 8-M-supertile rasterization keeps the B slice L2-resident per wave
    const int bid = blockIdx.x;
    const int grp = bid / (8 * NT_TILES);
    const int rem = bid % (8 * NT_TILES);
    const int mt  = grp * 8 + (rem & 7);
    const int nt  = rem >> 3;
    const int m0 = mt * BM;
    const int n0 = nt * BN;

    // A fragment base
    const int tm0 = (m0 >> 4) + warp_m * 4;
    const uint4* aptr = (const uint4*)g_af + ((size_t)tm0 * TK16) * 32 + lane;
    const int AMI = TK16 * 32;    // uint4 stride per m16 tile

    // B fragment base (pairs of n8 tiles)
    const int tnp0 = (n0 >> 4) + warp_n * 2;
    const uint4* bptr = (const uint4*)g_wf + ((size_t)tnp0 * TK16) * 32 + lane;
    const int BNP = TK16 * 32;    // uint4 stride per n8-pair

    float acc[4][4][4];
#pragma unroll
    for (int i = 0; i < 4; i++)
#pragma unroll
        for (int j = 0; j < 4; j++) {
            acc[i][j][0] = 0.f; acc[i][j][1] = 0.f;
            acc[i][j][2] = 0.f; acc[i][j][3] = 0.f;
        }

    uint4 af[2][4];        // [half][mi]
    uint4 bfA[2], bfB[2];  // [pair] for k16a / k16b

    // Prologue: load everything for t=0 (B first)
#pragma unroll
    for (int p = 0; p < 2; p++) bfA[p] = bptr[p * BNP];
#pragma unroll
    for (int p = 0; p < 2; p++) bfB[p] = bptr[p * BNP + 32];
#pragma unroll
    for (int mi = 0; mi < 4; mi++) af[0][mi] = aptr[mi * AMI];
#pragma unroll
    for (int mi = 0; mi < 4; mi++) af[1][mi] = aptr[mi * AMI + 32];

#pragma unroll 2
    for (int t = 0; t < NT; t++) {
        const int tn1 = (t + 1 < NT) ? t + 1 : t;   // clamp: last iter reloads t
        const int offA = (2 * tn1) * 32;
        const int offB = (2 * tn1 + 1) * 32;

        // ---- half 1: k16a — uses af[0], bfA ----
#pragma unroll
        for (int mi = 0; mi < 4; mi++) {
            mma16816(acc[mi][0], af[0][mi].x, af[0][mi].y, af[0][mi].z, af[0][mi].w,
                     bfA[0].x, bfA[0].y);
            mma16816(acc[mi][1], af[0][mi].x, af[0][mi].y, af[0][mi].z, af[0][mi].w,
                     bfA[0].z, bfA[0].w);
            mma16816(acc[mi][2], af[0][mi].x, af[0][mi].y, af[0][mi].z, af[0][mi].w,
                     bfA[1].x, bfA[1].y);
            mma16816(acc[mi][3], af[0][mi].x, af[0][mi].y, af[0][mi].z, af[0][mi].w,
                     bfA[1].z, bfA[1].w);
        }
        // reload (t+1): B first (L2 latency), then A (L1 hits)
#pragma unroll
        for (int p = 0; p < 2; p++) bfA[p] = bptr[p * BNP + offA];
#pragma unroll
        for (int mi = 0; mi < 4; mi++) af[0][mi] = aptr[mi * AMI + offA];

        // ---- half 2: k16b — uses af[1], bfB ----
#pragma unroll
        for (int mi = 0; mi < 4; mi++) {
            mma16816(acc[mi][0], af[1][mi].x, af[1][mi].y, af[1][mi].z, af[1][mi].w,
                     bfB[0].x, bfB[0].y);
            mma16816(acc[mi][1], af[1][mi].x, af[1][mi].y, af[1][mi].z, af[1][mi].w,
                     bfB[0].z, bfB[0].w);
            mma16816(acc[mi][2], af[1][mi].x, af[1][mi].y, af[1][mi].z, af[1][mi].w,
                     bfB[1].x, bfB[1].y);
            mma16816(acc[mi][3], af[1][mi].x, af[1][mi].y, af[1][mi].z, af[1][mi].w,
                     bfB[1].z, bfB[1].w);
        }
#pragma unroll
        for (int p = 0; p < 2; p++) bfB[p] = bptr[p * BNP + offB];
#pragma unroll
        for (int mi = 0; mi < 4; mi++) af[1][mi] = aptr[mi * AMI + offB];
    }

    // Epilogue: round through fp16, write float2
    const int g4 = lane >> 2, t4 = lane & 3;
#pragma unroll
    for (int mi = 0; mi < 4; mi++) {
#pragma unroll
        for (int nh = 0; nh < 4; nh++) {
            int row = m0 + warp_m * 64 + mi * 16 + g4;
            int col = n0 + warp_n * 32 + nh * 8 + t4 * 2;
            float2 v0, v1;
            v0.x = __half2float(__float2half_rn(acc[mi][nh][0]));
            v0.y = __half2float(__float2half_rn(acc[mi][nh][1]));
            v1.x = __half2float(__float2half_rn(acc[mi][nh][2]));
            v1.y = __half2float(__float2half_rn(acc[mi][nh][3]));
            *(float2*)(out + (size_t)row * N_DIM + col)       = v0;
            *(float2*)(out + (size_t)(row + 8) * N_DIM + col) = v1;
        }
    }
}

// ---------------------------------------------------------------------------
extern "C" void kernel_launch(void* const* d_in, const int* in_sizes, int n_in,
                              void* d_out, int out_size) {
    const float* x       = (const float*)d_in[0];
    const int*   qweight = (const int*)d_in[1];
    const int*   qzeros  = (const int*)d_in[2];
    const void*  scales  = d_in[3];
    float* out = (float*)d_out;

    // Fused prep: 512 convert blocks + 22016 dequant blocks
    prep_kernel<<<512 + 43 * KPACK, 256>>>(x, qweight, qzeros, scales);

    gemm_kernel<<<MT_TILES * NT_TILES, 256>>>(out);
}

// round 17
// speedup vs baseline: 1.0503x; 1.0503x over previous
#include <cuda_runtime.h>
#include <cuda_fp16.h>
#include <cstdint>
#include <cstddef>

// Problem constants
#define M_DIM 8192
#define K_DIM 4096
#define N_DIM 11008
#define NPACK (N_DIM / 8)
#define KPACK (K_DIM / 8)

#define TK16 (K_DIM / 16)      // 256 k16-tiles
#define TNP  (N_DIM / 16)      // 688 n8-pairs

// GEMM tiling: block 128x128x32, 8 warps (2M x 4N), warp tile 64x32
#define BM 128
#define BN 128
#define BK 32
#define NT (K_DIM / BK)        // 128
#define MT_TILES (M_DIM / BM)  // 64
#define NT_TILES (N_DIM / BN)  // 86

// Device scratch (allocation-free rule)
// A in mma-fragment order: [tm16][tk16][lane]{a0,a1,a2,a3} (16B per lane)
__device__ __half g_af[(size_t)M_DIM * K_DIM];
// W in PAIRED fragment order: [tnp16][tk16][lane]{b0_even,b1_even,b0_odd,b1_odd}
__device__ __half g_wf[(size_t)K_DIM * N_DIM];

// ---------------------------------------------------------------------------
// Fused prep kernel.
// Blocks [0,512): convert x -> A-fragment fp16 (verified R13).
// Blocks [512, 512+22016): dequant W -> paired-fragment fp16, one thread per
// output uint4 => fully coalesced STG.128 (512B per warp).
//   thread (tnp, tk16, lane): p = lane&3, n7 = lane>>2
//   pr0 = 2*tk16, pr1 = pr0+1; ne = tnp*16+n7, no = ne+8; g = tk16>>3
//   16B = halves[odd*4 + regsel*2 + kh] with nibbles j = 2p+kh of row pr_regsel
// ---------------------------------------------------------------------------
__global__ void prep_kernel(const float* __restrict__ x,
                            const int* __restrict__ qweight,
                            const int* __restrict__ qzeros,
                            const void* __restrict__ scales_raw) {
    if (blockIdx.x < 512) {
        // ---- convert_x part ----
        const int tm   = blockIdx.x;              // 0..511
        const int lane = threadIdx.x & 31;
        const int tkb  = threadIdx.x >> 5;        // 0..7
        const int r = lane >> 2, c = lane & 3;
        const int m0 = tm * 16;

        const float* row0 = x + (size_t)(m0 + r) * K_DIM + 2 * c;
        const float* row8 = row0 + (size_t)8 * K_DIM;
        uint4* dst = (uint4*)g_af + ((size_t)tm * TK16) * 32 + lane;

#pragma unroll 4
        for (int tk16 = tkb; tk16 < TK16; tk16 += 8) {
            const int k0 = tk16 * 16;
            float2 f0 = *(const float2*)(row0 + k0);
            float2 f1 = *(const float2*)(row8 + k0);
            float2 f2 = *(const float2*)(row0 + k0 + 8);
            float2 f3 = *(const float2*)(row8 + k0 + 8);
            __half2 h0 = __floats2half2_rn(f0.x, f0.y);
            __half2 h1 = __floats2half2_rn(f1.x, f1.y);
            __half2 h2 = __floats2half2_rn(f2.x, f2.y);
            __half2 h3 = __floats2half2_rn(f3.x, f3.y);
            uint4 u;
            u.x = *(uint32_t*)&h0; u.y = *(uint32_t*)&h1;
            u.z = *(uint32_t*)&h2; u.w = *(uint32_t*)&h3;
            dst[(size_t)tk16 * 32] = u;
        }
    } else {
        // ---- dequant part: coalesced 16B stores ----
        const int idx  = blockIdx.x - 512;        // 0..22015
        const int tnp  = idx % TNP;               // 0..687
        const int tkg  = idx / TNP;               // 0..31
        const int lane = threadIdx.x & 31;
        const int w    = threadIdx.x >> 5;        // 0..7
        const int tk16 = tkg * 8 + w;             // 0..255

        const int p  = lane & 3;
        const int n7 = lane >> 2;
        const int pr0 = 2 * tk16, pr1 = pr0 + 1;
        const int ne = tnp * 16 + n7, no = ne + 8;
        const int g  = tk16 >> 3;

        const float* sf = (const float*)scales_raw;
        float probe = sf[0];
        bool is_f32 = (probe > 5e-4f && probe < 5e-2f);

        uint32_t qe0 = (uint32_t)qweight[(size_t)pr0 * N_DIM + ne];
        uint32_t qe1 = (uint32_t)qweight[(size_t)pr1 * N_DIM + ne];
        uint32_t qo0 = (uint32_t)qweight[(size_t)pr0 * N_DIM + no];
        uint32_t qo1 = (uint32_t)qweight[(size_t)pr1 * N_DIM + no];

        uint32_t zqe = (uint32_t)qzeros[(size_t)g * NPACK + (ne >> 3)];
        uint32_t zqo = (uint32_t)qzeros[(size_t)g * NPACK + (no >> 3)];
        float ze = (float)((zqe >> (4 * (ne & 7))) & 15u);
        float zo = (float)((zqo >> (4 * (no & 7))) & 15u);
        float se = is_f32 ? sf[(size_t)g * N_DIM + ne]
                          : __half2float(((const __half*)scales_raw)[(size_t)g * N_DIM + ne]);
        float so = is_f32 ? sf[(size_t)g * N_DIM + no]
                          : __half2float(((const __half*)scales_raw)[(size_t)g * N_DIM + no]);

        const int j0 = 2 * p, j1 = 2 * p + 1;
        __half2 h0 = __floats2half2_rn(((float)((qe0 >> (4*j0)) & 15u) - ze) * se,
                                       ((float)((qe0 >> (4*j1)) & 15u) - ze) * se);
        __half2 h1 = __floats2half2_rn(((float)((qe1 >> (4*j0)) & 15u) - ze) * se,
                                       ((float)((qe1 >> (4*j1)) & 15u) - ze) * se);
        __half2 h2 = __floats2half2_rn(((float)((qo0 >> (4*j0)) & 15u) - zo) * so,
                                       ((float)((qo0 >> (4*j1)) & 15u) - zo) * so);
        __half2 h3 = __floats2half2_rn(((float)((qo1 >> (4*j0)) & 15u) - zo) * so,
                                       ((float)((qo1 >> (4*j1)) & 15u) - zo) * so);
        uint4 u;
        u.x = *(uint32_t*)&h0; u.y = *(uint32_t*)&h1;
        u.z = *(uint32_t*)&h2; u.w = *(uint32_t*)&h3;
        ((uint4*)g_wf)[((size_t)tnp * TK16 + tk16) * 32 + lane] = u;
    }
}

// ---------------------------------------------------------------------------
// mma helper
// ---------------------------------------------------------------------------
__device__ __forceinline__ void mma16816(float* c, uint32_t a0, uint32_t a1,
                                         uint32_t a2, uint32_t a3,
                                         uint32_t b0, uint32_t b1) {
    asm volatile(
        "mma.sync.aligned.m16n8k16.row.col.f32.f16.f16.f32 "
        "{%0,%1,%2,%3}, {%4,%5,%6,%7}, {%8,%9}, {%0,%1,%2,%3};"
        : "+f"(c[0]), "+f"(c[1]), "+f"(c[2]), "+f"(c[3])
        : "r"(a0), "r"(a1), "r"(a2), "r"(a3), "r"(b0), "r"(b1));
}

// ---------------------------------------------------------------------------
// Kernel 2: fragment GEMM, software-pipelined (B loads lead), last iter peeled.
// ---------------------------------------------------------------------------
__global__ __launch_bounds__(256, 2)
void gemm_kernel(float* __restrict__ out) {
    const int tid  = threadIdx.x;
    const int lane = tid & 31;
    const int wid  = tid >> 5;
    const int warp_m = wid & 1;    // 0..1 (64 rows = 4 m16 tiles each)
    const int warp_n = wid >> 1;   // 0..3 (32 cols = 2 n8-pairs each)

    // 8-M-supertile rasterization keeps the B slice L2-resident per wave
    const int bid = blockIdx.x;
    const int grp = bid / (8 * NT_TILES);
    const int rem = bid % (8 * NT_TILES);
    const int mt  = grp * 8 + (rem & 7);
    const int nt  = rem >> 3;
    const int m0 = mt * BM;
    const int n0 = nt * BN;

    // A fragment base
    const int tm0 = (m0 >> 4) + warp_m * 4;
    const uint4* aptr = (const uint4*)g_af + ((size_t)tm0 * TK16) * 32 + lane;
    const int AMI = TK16 * 32;    // uint4 stride per m16 tile

    // B fragment base (pairs of n8 tiles)
    const int tnp0 = (n0 >> 4) + warp_n * 2;
    const uint4* bptr = (const uint4*)g_wf + ((size_t)tnp0 * TK16) * 32 + lane;
    const int BNP = TK16 * 32;    // uint4 stride per n8-pair

    float acc[4][4][4];
#pragma unroll
    for (int i = 0; i < 4; i++)
#pragma unroll
        for (int j = 0; j < 4; j++) {
            acc[i][j][0] = 0.f; acc[i][j][1] = 0.f;
            acc[i][j][2] = 0.f; acc[i][j][3] = 0.f;
        }

    uint4 af[2][4];        // [half][mi]
    uint4 bfA[2], bfB[2];  // [pair] for k16a / k16b

    // Prologue: load everything for t=0 (B first)
#pragma unroll
    for (int p = 0; p < 2; p++) bfA[p] = bptr[p * BNP];
#pragma unroll
    for (int p = 0; p < 2; p++) bfB[p] = bptr[p * BNP + 32];
#pragma unroll
    for (int mi = 0; mi < 4; mi++) af[0][mi] = aptr[mi * AMI];
#pragma unroll
    for (int mi = 0; mi < 4; mi++) af[1][mi] = aptr[mi * AMI + 32];

#pragma unroll 2
    for (int t = 0; t < NT - 1; t++) {
        const int offA = (2 * (t + 1)) * 32;
        const int offB = (2 * (t + 1) + 1) * 32;

        // ---- half 1: k16a — uses af[0], bfA ----
#pragma unroll
        for (int mi = 0; mi < 4; mi++) {
            mma16816(acc[mi][0], af[0][mi].x, af[0][mi].y, af[0][mi].z, af[0][mi].w,
                     bfA[0].x, bfA[0].y);
            mma16816(acc[mi][1], af[0][mi].x, af[0][mi].y, af[0][mi].z, af[0][mi].w,
                     bfA[0].z, bfA[0].w);
            mma16816(acc[mi][2], af[0][mi].x, af[0][mi].y, af[0][mi].z, af[0][mi].w,
                     bfA[1].x, bfA[1].y);
            mma16816(acc[mi][3], af[0][mi].x, af[0][mi].y, af[0][mi].z, af[0][mi].w,
                     bfA[1].z, bfA[1].w);
        }
        // reload (t+1): B first (L2 latency), then A (L1 hits)
#pragma unroll
        for (int p = 0; p < 2; p++) bfA[p] = bptr[p * BNP + offA];
#pragma unroll
        for (int mi = 0; mi < 4; mi++) af[0][mi] = aptr[mi * AMI + offA];

        // ---- half 2: k16b — uses af[1], bfB ----
#pragma unroll
        for (int mi = 0; mi < 4; mi++) {
            mma16816(acc[mi][0], af[1][mi].x, af[1][mi].y, af[1][mi].z, af[1][mi].w,
                     bfB[0].x, bfB[0].y);
            mma16816(acc[mi][1], af[1][mi].x, af[1][mi].y, af[1][mi].z, af[1][mi].w,
                     bfB[0].z, bfB[0].w);
            mma16816(acc[mi][2], af[1][mi].x, af[1][mi].y, af[1][mi].z, af[1][mi].w,
                     bfB[1].x, bfB[1].y);
            mma16816(acc[mi][3], af[1][mi].x, af[1][mi].y, af[1][mi].z, af[1][mi].w,
                     bfB[1].z, bfB[1].w);
        }
#pragma unroll
        for (int p = 0; p < 2; p++) bfB[p] = bptr[p * BNP + offB];
#pragma unroll
        for (int mi = 0; mi < 4; mi++) af[1][mi] = aptr[mi * AMI + offB];
    }

    // Peeled last iteration (no reloads)
#pragma unroll
    for (int mi = 0; mi < 4; mi++) {
        mma16816(acc[mi][0], af[0][mi].x, af[0][mi].y, af[0][mi].z, af[0][mi].w,
                 bfA[0].x, bfA[0].y);
        mma16816(acc[mi][1], af[0][mi].x, af[0][mi].y, af[0][mi].z, af[0][mi].w,
                 bfA[0].z, bfA[0].w);
        mma16816(acc[mi][2], af[0][mi].x, af[0][mi].y, af[0][mi].z, af[0][mi].w,
                 bfA[1].x, bfA[1].y);
        mma16816(acc[mi][3], af[0][mi].x, af[0][mi].y, af[0][mi].z, af[0][mi].w,
                 bfA[1].z, bfA[1].w);
    }
#pragma unroll
    for (int mi = 0; mi < 4; mi++) {
        mma16816(acc[mi][0], af[1][mi].x, af[1][mi].y, af[1][mi].z, af[1][mi].w,
                 bfB[0].x, bfB[0].y);
        mma16816(acc[mi][1], af[1][mi].x, af[1][mi].y, af[1][mi].z, af[1][mi].w,
                 bfB[0].z, bfB[0].w);
        mma16816(acc[mi][2], af[1][mi].x, af[1][mi].y, af[1][mi].z, af[1][mi].w,
                 bfB[1].x, bfB[1].y);
        mma16816(acc[mi][3], af[1][mi].x, af[1][mi].y, af[1][mi].z, af[1][mi].w,
                 bfB[1].z, bfB[1].w);
    }

    // Epilogue: round through fp16, write float2
    const int g4 = lane >> 2, t4 = lane & 3;
#pragma unroll
    for (int mi = 0; mi < 4; mi++) {
#pragma unroll
        for (int nh = 0; nh < 4; nh++) {
            int row = m0 + warp_m * 64 + mi * 16 + g4;
            int col = n0 + warp_n * 32 + nh * 8 + t4 * 2;
            float2 v0, v1;
            v0.x = __half2float(__float2half_rn(acc[mi][nh][0]));
            v0.y = __half2float(__float2half_rn(acc[mi][nh][1]));
            v1.x = __half2float(__float2half_rn(acc[mi][nh][2]));
            v1.y = __half2float(__float2half_rn(acc[mi][nh][3]));
            *(float2*)(out + (size_t)row * N_DIM + col)       = v0;
            *(float2*)(out + (size_t)(row + 8) * N_DIM + col) = v1;
        }
    }
}

// ---------------------------------------------------------------------------
extern "C" void kernel_launch(void* const* d_in, const int* in_sizes, int n_in,
                              void* d_out, int out_size) {
    const float* x       = (const float*)d_in[0];
    const int*   qweight = (const int*)d_in[1];
    const int*   qzeros  = (const int*)d_in[2];
    const void*  scales  = d_in[3];
    float* out = (float*)d_out;

    // Fused prep: 512 convert blocks + 688*32 dequant blocks
    prep_kernel<<<512 + TNP * 32, 256>>>(x, qweight, qzeros, scales);

    gemm_kernel<<<MT_TILES * NT_TILES, 256>>>(out);
}